// round 4
// baseline (speedup 1.0000x reference)
#include <cuda_runtime.h>
#include <cuda_bf16.h>

#define NVSEG 29000
#define HWSZ  (1024 * 1024)
#define BATCH 16
#define BHW   (BATCH * HWSZ)

#define NPIX4 (BHW / 4)          // work items (4 pixels each)
#define PERSIST_BLOCKS 912       // 152 SMs * 6 CTAs co-resident (single wave)

// Scratch (__device__ globals are zero-initialized at module load).
// g_acc[v] = {sum_c0, sum_c1, sum_c2, count}. Invariant: zero at kernel_launch
// entry — replaced_kernel re-zeroes it after consuming, keeping every call
// (correctness run, capture, replays) identical.
__device__ float4 g_acc[NVSEG];
__device__ float4 g_rep[NVSEG];

// Pass 1: segment sums + counts. Persistent grid-stride, 4 px/iter,
// one float4 RED per pixel. img/seg are single-use -> streaming loads.
__global__ __launch_bounds__(256, 6) void accumulate_kernel(
    const float* __restrict__ img, const int* __restrict__ seg)
{
    const long stride = (long)gridDim.x * blockDim.x;
    for (long t = (long)blockIdx.x * blockDim.x + threadIdx.x; t < NPIX4; t += stride) {
        const long p = t << 2;
        const int  b = (int)(t >> 18);          // p >> 20
        const long rem = p & (HWSZ - 1);
        const float* base = img + (long)b * 3 * HWSZ + rem;

        const int4   s  = __ldcs((const int4*)(seg + p));
        const float4 c0 = __ldcs((const float4*)(base + 0 * HWSZ));
        const float4 c1 = __ldcs((const float4*)(base + 1 * HWSZ));
        const float4 c2 = __ldcs((const float4*)(base + 2 * HWSZ));

        atomicAdd(&g_acc[s.x], make_float4(c0.x, c1.x, c2.x, 1.0f));
        atomicAdd(&g_acc[s.y], make_float4(c0.y, c1.y, c2.y, 1.0f));
        atomicAdd(&g_acc[s.z], make_float4(c0.z, c1.z, c2.z, 1.0f));
        atomicAdd(&g_acc[s.w], make_float4(c0.w, c1.w, c2.w, 1.0f));
    }
}

// Pass 2: rep[v] = fV[v] - sums[v]/max(cnt,1); then reset g_acc[v] = 0 so the
// next kernel_launch call starts from the zero invariant.
__global__ __launch_bounds__(256) void replaced_kernel(const float* __restrict__ fV) {
    int v = blockIdx.x * blockDim.x + threadIdx.x;
    if (v >= NVSEG) return;
    float4 a = g_acc[v];
    g_acc[v] = make_float4(0.f, 0.f, 0.f, 0.f);
    float inv = 1.0f / fmaxf(a.w, 1.0f);
    float4 r;
    r.x = fV[3 * v + 0] - a.x * inv;
    r.y = fV[3 * v + 1] - a.y * inv;
    r.z = fV[3 * v + 2] - a.z * inv;
    r.w = 0.f;
    g_rep[v] = r;
}

// Pass 3: out[p,c] = pixels[p,c] + rep[seg[p],c]. Persistent grid-stride.
// Streaming img/seg/out keeps L1 free so g_rep (464 KB) is partially
// L1-resident; gathers (the long pole) issued first each iteration.
__global__ __launch_bounds__(256, 6) void output_kernel(
    const float* __restrict__ img, const int* __restrict__ seg,
    float* __restrict__ out)
{
    const long stride = (long)gridDim.x * blockDim.x;
    for (long t = (long)blockIdx.x * blockDim.x + threadIdx.x; t < NPIX4; t += stride) {
        const long p = t << 2;
        const int  b = (int)(t >> 18);
        const long rem = p & (HWSZ - 1);
        const float* base = img + (long)b * 3 * HWSZ + rem;

        const int4 s = __ldcs((const int4*)(seg + p));

        const float4 r0 = g_rep[s.x];
        const float4 r1 = g_rep[s.y];
        const float4 r2 = g_rep[s.z];
        const float4 r3 = g_rep[s.w];

        const float4 c0 = __ldcs((const float4*)(base + 0 * HWSZ));
        const float4 c1 = __ldcs((const float4*)(base + 1 * HWSZ));
        const float4 c2 = __ldcs((const float4*)(base + 2 * HWSZ));

        float4 o0, o1, o2;
        o0.x = c0.x + r0.x;  o0.y = c1.x + r0.y;  o0.z = c2.x + r0.z;  o0.w = c0.y + r1.x;
        o1.x = c1.y + r1.y;  o1.y = c2.y + r1.z;  o1.z = c0.z + r2.x;  o1.w = c1.z + r2.y;
        o2.x = c2.z + r2.z;  o2.y = c0.w + r3.x;  o2.z = c1.w + r3.y;  o2.w = c2.w + r3.z;

        float4* dst = (float4*)(out + p * 3);   // 12t floats -> 16B aligned
        __stcs(dst + 0, o0);
        __stcs(dst + 1, o1);
        __stcs(dst + 2, o2);
    }
}

extern "C" void kernel_launch(void* const* d_in, const int* in_sizes, int n_in,
                              void* d_out, int out_size)
{
    const float* img = (const float*)d_in[0];
    const int*   seg = (const int*)d_in[1];
    const float* fV  = (const float*)d_in[2];
    float* out = (float*)d_out;

    const int threads = 256;
    const int nvBlocks = (NVSEG + threads - 1) / threads;

    accumulate_kernel<<<PERSIST_BLOCKS, threads>>>(img, seg);
    replaced_kernel<<<nvBlocks, threads>>>(fV);
    output_kernel<<<PERSIST_BLOCKS, threads>>>(img, seg, out);
}